// round 11
// baseline (speedup 1.0000x reference)
#include <cuda_runtime.h>
#include <math.h>

// Problem-fixed shapes
#define H   4096
#define W   4096
#define W2  8192

#define SCONST       1e-12f
#define EPS_V_FLOOR  (1e-32f / 6.0f)
#define PI_D         (3.14159265358979323846f / 1.1f)
#define PI_2         1.57079632679489662f

#define TILE 32
#define SM_W 36                      // TILE + 2*2 halo
#define NBX  (W / TILE)              // 128
#define NBY  (H / TILE)              // 128
#define NBLK (NBX * NBY)             // 16384

__device__ double g_partials[NBLK];
__device__ unsigned int g_ticket;    // zero-init; reset by last block each call

// ---------------------------------------------------------------------------
// Math tail: derivatives -> penalty value. (Validated: rel_err == 0.0 in R9)
// ---------------------------------------------------------------------------
__device__ __forceinline__ float penalty_val(float ex, float ey,
                                             float exx, float exy, float eyy,
                                             float c) {
    const float exs = ex + SCONST;
    const float eys = ey + SCONST;
    const float x2 = exs * exs;
    const float y2 = eys * eys;
    const float ev2 = x2 + y2;
    const float rinv = rsqrtf(ev2);
    const float ev = fmaxf(ev2 * rinv, EPS_V_FLOOR);
    float num = fmaf(y2, exx, x2 * eyy);
    num = fmaf(-2.0f * (exs * eys), exy, num);
    const float rinv3 = (rinv * rinv) * rinv;
    const float kabs = fabsf(num) * rinv3;

    // |atan(ev/c)| = atan(ev/|c|), reflected so the poly arg is in [0,1].
    const float ac = fabsf(c);
    const float z = __fdividef(fminf(ev, ac), fmaxf(ev, ac));
    const float w = z * z;
    float p = fmaf(w, -0.0040540580f, 0.0218612288f);
    p = fmaf(w, p, -0.0559098861f);
    p = fmaf(w, p, 0.0964200441f);
    p = fmaf(w, p, -0.1390853351f);
    p = fmaf(w, p, 0.1994653599f);
    p = fmaf(w, p, -0.3332985605f);
    p = fmaf(w, p, 0.9999993329f);
    float t = z * p;
    t = (ev > ac) ? (PI_2 - t) : t;

    return fmaxf(fmaf(kabs, t, -PI_D), 0.0f);  // fmaxf(NaN,0)=0 == nansum drop
}

// ---------------------------------------------------------------------------
// Generic (boundary-exact) path: composed one-sided operators on the
// column-mirrored [H, 2W] field. Cold: only j<2 or i within 2 of top/bottom.
// ---------------------------------------------------------------------------
__device__ __forceinline__ float Mld(const float* __restrict__ e, int i, int g) {
    int j = g < W ? g : (W2 - 1 - g);
    return __ldg(e + (size_t)i * W + j);
}

__device__ __noinline__ float generic_val(const float* __restrict__ e,
                                          int i, int j, float d) {
    const float rd = 1.0f / d;
    const float r2d = 0.5f / d;

    auto EXg = [&](int ii, int g) -> float {
        if (ii == 0)     return (Mld(e, 1, g) - Mld(e, 0, g)) * rd;
        if (ii == H - 1) return (Mld(e, H - 1, g) - Mld(e, H - 2, g)) * rd;
        return (Mld(e, ii + 1, g) - Mld(e, ii - 1, g)) * r2d;
    };
    auto EYg = [&](int ii, int g) -> float {
        if (g == 0) return (Mld(e, ii, 1) - Mld(e, ii, 0)) * rd;
        return (Mld(e, ii, g + 1) - Mld(e, ii, g - 1)) * r2d;
    };

    const float ex = EXg(i, j);
    const float ey = EYg(i, j);
    float exx, exy, eyy;
    if (i == 0)
        exx = (EXg(1, j) - EXg(0, j)) * rd;
    else if (i == H - 1)
        exx = (EXg(H - 1, j) - EXg(H - 2, j)) * rd;
    else
        exx = (EXg(i + 1, j) - EXg(i - 1, j)) * r2d;
    if (j == 0) {
        exy = (EXg(i, 1) - EXg(i, 0)) * rd;
        eyy = (EYg(i, 1) - EYg(i, 0)) * rd;
    } else {
        exy = (EXg(i, j + 1) - EXg(i, j - 1)) * r2d;
        eyy = (EYg(i, j + 1) - EYg(i, j - 1)) * r2d;
    }
    const float c = __ldg(e + (size_t)i * W + j);
    return penalty_val(ex, ey, exx, exy, eyy, c);
}

__device__ __forceinline__ float warp_reduce_f(float v) {
#pragma unroll
    for (int o = 16; o > 0; o >>= 1)
        v += __shfl_xor_sync(0xffffffffu, v, o);
    return v;
}

// ---------------------------------------------------------------------------
// Main kernel: 32x32 output tile from a 36x36 smem tile. Each thread computes
// 4 consecutive rows of one column: 28 LDS -> 4 outputs (7 LDS/elem), with
// 4 independent math chains for ILP. Final reduction fused via ticket.
// ---------------------------------------------------------------------------
__global__ __launch_bounds__(256, 4)
void curve_kernel(const float* __restrict__ eps, const float* __restrict__ gs,
                  float* __restrict__ out) {
    __shared__ float tile[SM_W * SM_W];
    __shared__ double wpart[8];
    __shared__ double smr[256];
    __shared__ bool islast;

    const int tid = threadIdx.x;
    const int tx  = tid & 31;            // column within tile
    const int ty  = tid >> 5;            // 4-row group index (0..7)
    const int bi0 = blockIdx.y * TILE;
    const int bj0 = blockIdx.x * TILE;

    const float d    = __ldg(gs);
    const float r2d  = 0.5f / d;
    const float r2d2 = r2d * r2d;

    // Cooperative halo-tile fill: rows clamped (clamped rows feed only
    // outputs the generic path overrides), columns >= W use the mirror map.
#pragma unroll
    for (int k = 0; k < 6; k++) {
        int idx = tid + k * 256;
        if (idx < SM_W * SM_W) {
            int r  = idx / SM_W;
            int cl = idx - r * SM_W;
            int gi = bi0 - 2 + r;
            gi = gi < 0 ? 0 : (gi > H - 1 ? H - 1 : gi);
            int gj = bj0 - 2 + cl;
            gj = gj < 0 ? 0 : (gj < W ? gj : (W2 - 1 - gj));
            tile[idx] = __ldg(eps + (size_t)gi * W + gj);
        }
    }
    __syncthreads();

#define S(a, b) tile[(a) * SM_W + (b)]

    const int i0  = bi0 + ty * 4;        // first of this thread's 4 rows
    const int j   = bj0 + tx;
    const int si0 = ty * 4 + 2;          // smem row of i0
    const int sj  = tx + 2;

    // 28 shared loads serve 4 outputs (lanes -> consecutive banks, no conflicts)
    float cC[8], cL[6], cR[6], cL2[4], cR2[4];
#pragma unroll
    for (int r = 0; r < 8; r++) cC[r] = S(si0 - 2 + r, sj);
#pragma unroll
    for (int r = 0; r < 6; r++) {
        cL[r] = S(si0 - 1 + r, sj - 1);
        cR[r] = S(si0 - 1 + r, sj + 1);
    }
#pragma unroll
    for (int r = 0; r < 4; r++) {
        cL2[r] = S(si0 + r, sj - 2);
        cR2[r] = S(si0 + r, sj + 2);
    }
#undef S

    float acc = 0.0f;
    // Fast iff all 4 rows have central i-stencils and j >= 2. The mirrored
    // field is 2W wide, so j has NO upper bound for central differences —
    // the mirror halo in the tile is exactly the concatenated field.
    const bool fast = (i0 >= 2) & (i0 + 3 <= H - 3) & (j >= 2);

    if (fast) {
#pragma unroll
        for (int q = 0; q < 4; q++) {
            const float c   = cC[q + 2];
            const float ex  = (cC[q + 3] - cC[q + 1]) * r2d;
            const float ey  = (cR[q + 1] - cL[q + 1]) * r2d;
            const float exx = (fmaf(-2.0f, c, cC[q + 4]) + cC[q]) * r2d2;
            const float eyy = (fmaf(-2.0f, c, cR2[q]) + cL2[q]) * r2d2;
            const float exy = ((cR[q + 2] - cR[q]) - (cL[q + 2] - cL[q])) * r2d2;
            acc += penalty_val(ex, ey, exx, exy, eyy, c);
        }
    } else {
#pragma unroll
        for (int q = 0; q < 4; q++) {
            const int i = i0 + q;
            if ((i >= 2) & (i <= H - 3) & (j >= 2)) {
                const float c   = cC[q + 2];
                const float ex  = (cC[q + 3] - cC[q + 1]) * r2d;
                const float ey  = (cR[q + 1] - cL[q + 1]) * r2d;
                const float exx = (fmaf(-2.0f, c, cC[q + 4]) + cC[q]) * r2d2;
                const float eyy = (fmaf(-2.0f, c, cR2[q]) + cL2[q]) * r2d2;
                const float exy = ((cR[q + 2] - cR[q]) - (cL[q + 2] - cL[q])) * r2d2;
                acc += penalty_val(ex, ey, exx, exy, eyy, c);
            } else {
                acc += generic_val(eps, i, j, d);
            }
        }
    }

    // Block reduction
    const float ws = warp_reduce_f(acc);
    if ((tid & 31) == 0) wpart[tid >> 5] = (double)ws;
    __syncthreads();
    if (tid == 0) {
        double s = 0.0;
#pragma unroll
        for (int w = 0; w < 8; w++) s += wpart[w];
        g_partials[blockIdx.y * NBX + blockIdx.x] = s;
        __threadfence();
        unsigned old = atomicAdd(&g_ticket, 1u);
        islast = (old == NBLK - 1);
    }
    __syncthreads();

    // Last block performs the final deterministic reduction
    if (islast) {
        __threadfence();
        double s = 0.0;
        for (int i = tid; i < NBLK; i += 256) s += g_partials[i];
        smr[tid] = s;
        __syncthreads();
        for (int off = 128; off > 0; off >>= 1) {
            if (tid < off) smr[tid] += smr[tid + off];
            __syncthreads();
        }
        if (tid == 0) {
            // x2: mirror-symmetric halves contribute identically; ALPHA = 1
            out[0] = (float)(smr[0] * 2.0 * (double)d * (double)d);
            g_ticket = 0;                // reset for graph replay
        }
    }
}

extern "C" void kernel_launch(void* const* d_in, const int* in_sizes, int n_in,
                              void* d_out, int out_size) {
    const float* eps = (const float*)d_in[0];
    const float* gs  = (const float*)d_in[1];
    float* out = (float*)d_out;

    dim3 grid(NBX, NBY);     // 128 x 128 = 16384 blocks
    dim3 block(256);
    curve_kernel<<<grid, block>>>(eps, gs, out);
}

// round 12
// speedup vs baseline: 2.3223x; 2.3223x over previous
#include <cuda_runtime.h>
#include <math.h>

// Problem-fixed shapes
#define H   4096
#define W   4096
#define W2  8192

#define SCONST       1e-12f
#define EPS_V_FLOOR  (1e-32f / 6.0f)
#define PI_D         (3.14159265358979323846f / 1.1f)
#define PI_2         1.57079632679489662f

#define TILE_I 64
#define TILE_J 32
#define SM_H   68                    // TILE_I + 4
#define SM_W   36                    // TILE_J + 4
#define NBX    (W / TILE_J)          // 128
#define NBY    (H / TILE_I)          // 64
#define NBLK   (NBX * NBY)           // 8192

__device__ double g_partials[NBLK];
__device__ unsigned int g_ticket;    // zero-init; reset by last block each call

// ---------------------------------------------------------------------------
// Math tail: derivatives -> penalty value. (Validated: rel_err == 0.0)
// ---------------------------------------------------------------------------
__device__ __forceinline__ float penalty_val(float ex, float ey,
                                             float exx, float exy, float eyy,
                                             float c) {
    const float exs = ex + SCONST;
    const float eys = ey + SCONST;
    const float x2 = exs * exs;
    const float y2 = eys * eys;
    const float ev2 = x2 + y2;
    const float rinv = rsqrtf(ev2);
    const float ev = fmaxf(ev2 * rinv, EPS_V_FLOOR);
    float num = fmaf(y2, exx, x2 * eyy);
    num = fmaf(-2.0f * (exs * eys), exy, num);
    const float rinv3 = (rinv * rinv) * rinv;
    const float kabs = fabsf(num) * rinv3;

    // |atan(ev/c)| = atan(ev/|c|), reflected so the poly arg is in [0,1].
    const float ac = fabsf(c);
    const float z = __fdividef(fminf(ev, ac), fmaxf(ev, ac));
    const float w = z * z;
    float p = fmaf(w, -0.0040540580f, 0.0218612288f);
    p = fmaf(w, p, -0.0559098861f);
    p = fmaf(w, p, 0.0964200441f);
    p = fmaf(w, p, -0.1390853351f);
    p = fmaf(w, p, 0.1994653599f);
    p = fmaf(w, p, -0.3332985605f);
    p = fmaf(w, p, 0.9999993329f);
    float t = z * p;
    t = (ev > ac) ? (PI_2 - t) : t;

    return fmaxf(fmaf(kabs, t, -PI_D), 0.0f);  // fmaxf(NaN,0)=0 == nansum drop
}

__device__ __forceinline__ float warp_reduce_f(float v) {
#pragma unroll
    for (int o = 16; o > 0; o >>= 1)
        v += __shfl_xor_sync(0xffffffffu, v, o);
    return v;
}

// ---------------------------------------------------------------------------
// Main kernel: 64x32 output strip from a 68x36 smem tile. Each thread does 8
// row-strided outputs of one column, 13 short-lived LDS per output (no
// register-cached neighborhoods -> no spills; this is the R3 pattern that
// measured fastest). Boundary elements use the composed one-sided operators
// inline on the same smem tile. Final reduction fused via ticket.
// ---------------------------------------------------------------------------
__global__ __launch_bounds__(256, 5)
void curve_kernel(const float* __restrict__ eps, const float* __restrict__ gs,
                  float* __restrict__ out) {
    __shared__ float tile[SM_H * SM_W];
    __shared__ double wpart[8];
    __shared__ double smr[256];
    __shared__ bool islast;

    const int tid = threadIdx.x;
    const int tx  = tid & 31;            // column within tile
    const int ty  = tid >> 5;            // row-group base (0..7)
    const int bi0 = blockIdx.y * TILE_I;
    const int bj0 = blockIdx.x * TILE_J;

    const float d    = __ldg(gs);
    const float rd   = 1.0f / d;
    const float r2d  = 0.5f / d;
    const float r2d2 = r2d * r2d;

    // Cooperative halo fill: rows clamped (clamped rows feed only outputs the
    // boundary path overrides), columns >= W use the reference's mirror map.
#pragma unroll
    for (int k = 0; k < 10; k++) {
        int idx = tid + k * 256;
        if (idx < SM_H * SM_W) {
            int r  = idx / SM_W;
            int cl = idx - r * SM_W;
            int gi = bi0 - 2 + r;
            gi = gi < 0 ? 0 : (gi > H - 1 ? H - 1 : gi);
            int gj = bj0 - 2 + cl;
            gj = gj < 0 ? 0 : (gj < W ? gj : (W2 - 1 - gj));
            tile[idx] = __ldg(eps + (size_t)gi * W + gj);
        }
    }
    __syncthreads();

#define S(a, b) tile[(a) * SM_W + (b)]

    const int j  = bj0 + tx;
    const int sj = tx + 2;
    float acc = 0.0f;

#pragma unroll
    for (int rr = 0; rr < 8; rr++) {
        const int li = ty + rr * 8;
        const int i  = bi0 + li;
        const int si = li + 2;

        const float c = S(si, sj);
        float ex, ey, exx, exy, eyy;

        if ((i >= 2) & (i <= H - 3) & (j >= 2)) {
            // Interior: central differences. The mirrored field is 2W wide, so
            // j has no upper bound (mirror columns are baked into the halo).
            ex  = (S(si + 1, sj) - S(si - 1, sj)) * r2d;
            ey  = (S(si, sj + 1) - S(si, sj - 1)) * r2d;
            exx = (fmaf(-2.0f, c, S(si + 2, sj)) + S(si - 2, sj)) * r2d2;
            eyy = (fmaf(-2.0f, c, S(si, sj + 2)) + S(si, sj - 2)) * r2d2;
            exy = ((S(si + 1, sj + 1) - S(si - 1, sj + 1)) -
                   (S(si + 1, sj - 1) - S(si - 1, sj - 1))) * r2d2;
        } else {
            // Boundary: composed one-sided operators (R3-exact).
            auto EXf = [&](int gi_, int a, int b) -> float {
                if (gi_ == 0)     return (S(a + 1, b) - S(a, b)) * rd;
                if (gi_ == H - 1) return (S(a, b) - S(a - 1, b)) * rd;
                return (S(a + 1, b) - S(a - 1, b)) * r2d;
            };
            auto EYf = [&](int gj_, int a, int b) -> float {
                if (gj_ == 0) return (S(a, b + 1) - S(a, b)) * rd;
                return (S(a, b + 1) - S(a, b - 1)) * r2d;  // gj_==W2-1 unreachable
            };
            ex = EXf(i, si, sj);
            ey = EYf(j, si, sj);
            if (i == 0)
                exx = (EXf(1, si + 1, sj) - EXf(0, si, sj)) * rd;
            else if (i == H - 1)
                exx = (EXf(H - 1, si, sj) - EXf(H - 2, si - 1, sj)) * rd;
            else
                exx = (EXf(i + 1, si + 1, sj) - EXf(i - 1, si - 1, sj)) * r2d;
            if (j == 0) {
                exy = (EXf(i, si, sj + 1) - EXf(i, si, sj)) * rd;
                eyy = (EYf(1, si, sj + 1) - EYf(0, si, sj)) * rd;
            } else {
                exy = (EXf(i, si, sj + 1) - EXf(i, si, sj - 1)) * r2d;
                eyy = (EYf(j + 1, si, sj + 1) - EYf(j - 1, si, sj - 1)) * r2d;
            }
        }

        acc += penalty_val(ex, ey, exx, exy, eyy, c);
    }

#undef S

    // Block reduction
    const float ws = warp_reduce_f(acc);
    if ((tid & 31) == 0) wpart[tid >> 5] = (double)ws;
    __syncthreads();
    if (tid == 0) {
        double s = 0.0;
#pragma unroll
        for (int w = 0; w < 8; w++) s += wpart[w];
        g_partials[blockIdx.y * NBX + blockIdx.x] = s;
        __threadfence();
        unsigned old = atomicAdd(&g_ticket, 1u);
        islast = (old == NBLK - 1);
    }
    __syncthreads();

    // Last block: deterministic final reduction (4-way ILP then tree)
    if (islast) {
        __threadfence();
        double s0 = 0.0, s1 = 0.0, s2 = 0.0, s3 = 0.0;
#pragma unroll
        for (int k = 0; k < NBLK / 1024; k++) {   // 8 iters of 4
            const int base = k * 1024 + tid;
            s0 += g_partials[base];
            s1 += g_partials[base + 256];
            s2 += g_partials[base + 512];
            s3 += g_partials[base + 768];
        }
        smr[tid] = (s0 + s1) + (s2 + s3);
        __syncthreads();
        for (int off = 128; off > 0; off >>= 1) {
            if (tid < off) smr[tid] += smr[tid + off];
            __syncthreads();
        }
        if (tid == 0) {
            // x2: mirror-symmetric halves contribute identically; ALPHA = 1
            out[0] = (float)(smr[0] * 2.0 * (double)d * (double)d);
            g_ticket = 0;                // reset for graph replay
        }
    }
}

extern "C" void kernel_launch(void* const* d_in, const int* in_sizes, int n_in,
                              void* d_out, int out_size) {
    const float* eps = (const float*)d_in[0];
    const float* gs  = (const float*)d_in[1];
    float* out = (float*)d_out;

    dim3 grid(NBX, NBY);     // 128 x 64 = 8192 blocks
    dim3 block(256);
    curve_kernel<<<grid, block>>>(eps, gs, out);
}